// round 13
// baseline (speedup 1.0000x reference)
#include <cuda_runtime.h>
#include <cstdint>

#define CCH   256
#define FH    50
#define FW    50
#define HW    (FH*FW)
#define OUTS  7
#define SPAN  3           // bilinear footprint per ROI axis (roi extent < 1 px)
#define EX    8           // extracted corner size (max index used is 5)
#define NPIX  (EX*EX)     // 64
#define NROI  1024
#define WREC  48          // floats per ROI weight record (42 w + 2 base + pad)
#define OBUF_FLOATS (128 * OUTS * OUTS)   // 6272 floats = 25088 B per block

// Extracted, channel-contiguous corner of the feature map: [64 pixels][256 ch].
__device__ float g_fmt[NPIX * CCH];
// Per-ROI weights: [n][0..20]=y wts (0.25 folded), [21..41]=x wts, [42]=rb, [43]=cb.
__device__ float g_wtab[NROI * WREC];

// ---------------------------------------------------------------------------
// Prep kernel: blocks 0..127 extract the 8x8 corner (channel-contiguous);
// blocks 128..239 compute per-ROI separable weights (one thread per (n,axis,o),
// arithmetic identical to the validated in-kernel setup). Fires PDL
// launch_dependents so roi_kernel can overlap its launch.
// ---------------------------------------------------------------------------
__global__ void prep_kernel(const float* __restrict__ fm,
                            const float* __restrict__ props) {
    const int b   = blockIdx.x;
    const int tid = threadIdx.x;
    if (b < 128) {
        // extract: pixel = b>>1 .. covers 64 pixels x 256 channels
        int pix = b >> 1;
        int c   = (b & 1) * 128 + tid;
        int fmo = (pix >> 3) * FW + (pix & 7);
        g_fmt[pix * CCH + c] = fm[c * HW + fmo];
    } else {
        int idx = (b - 128) * 128 + tid;            // 0..14335
        if (idx < NROI * 14) {
            const int n    = idx / 14;
            const int t    = idx % 14;
            const int axis = t >= OUTS;              // 0 = y, 1 = x
            const int o    = axis ? t - OUTS : t;
            const float sc = 1.0f / 256.0f;          // SCALE applied twice (exact)
            float a1 = __fmul_rn(props[n * 4 + (axis == 0 ? 1 : 0)], sc);
            float a2 = __fmul_rn(props[n * 4 + (axis == 0 ? 3 : 2)], sc);
            float roi   = fmaxf(__fadd_rn(a2, -a1), 1.0f);
            float binsz = __fdiv_rn(roi, 7.0f);
            const float Lf = 50.0f;
            const int   Li = 49;

            // base = i0 of sample 0 (i0 monotone in s).
            int base;
            {
                float v  = __fadd_rn(a1, __fmul_rn(binsz, 0.25f));
                float vc = fminf(fmaxf(v, 0.0f), Lf - 1.0f);
                base = min((int)floorf(vc), Li);
            }

            float w0 = 0.0f, w1 = 0.0f, w2 = 0.0f;
            #pragma unroll
            for (int k = 0; k < 2; k++) {
                int s = 2 * o + k;
                float g = ((float)s + 0.5f) * 0.5f;
                float v = __fadd_rn(a1, __fmul_rn(binsz, g));
                bool valid = (v >= -1.0f) && (v <= Lf);
                float vc = fminf(fmaxf(v, 0.0f), Lf - 1.0f);
                int i0 = min((int)floorf(vc), Li);
                int i1 = min(i0 + 1, Li);
                float l = vc - (float)i0;
                float h = 1.0f - l;
                if (!valid) { h = 0.0f; l = 0.0f; }
                int r0 = min(i0 - base, SPAN - 1);
                int r1 = min(i1 - base, SPAN - 1);
                if (r0 == 0) w0 += h; else if (r0 == 1) w1 += h; else w2 += h;
                if (r1 == 0) w0 += l; else if (r1 == 1) w1 += l; else w2 += l;
            }
            float f = (axis == 0) ? 0.25f : 1.0f;    // fold sr*sr mean into y wts
            float* rec = g_wtab + n * WREC + axis * 21 + o * SPAN;
            rec[0] = w0 * f; rec[1] = w1 * f; rec[2] = w2 * f;
            if (o == 0) g_wtab[n * WREC + 42 + axis] = (float)base;
        }
    }
    asm volatile("griddepcontrol.launch_dependents;");
}

// ---------------------------------------------------------------------------
// ROI-align kernel: grid N*2 (128-channel halves), 128 threads. All per-ROI
// setup is one 44-float table load; compute/staging/TMA identical to the
// validated R7 body.
// wsm: [0..20]=y wts, [21..41]=x wts, [42]=rb, [43]=cb.
// ---------------------------------------------------------------------------
__global__ __launch_bounds__(128, 8) void roi_kernel(float* __restrict__ out)
{
    __shared__ __align__(16) float obuf[OBUF_FLOATS];  // 25088 B staging
    __shared__ float wsm[44];

    const int n   = blockIdx.x >> 1;
    const int tid = threadIdx.x;

    // Wait for prep_kernel's g_wtab/g_fmt stores (PDL dependency point).
    asm volatile("griddepcontrol.wait;");

    if (tid < 44)
        wsm[tid] = g_wtab[n * WREC + tid];
    __syncthreads();

    const int ch = (blockIdx.x & 1) * 128 + tid;
    const int rb = (int)wsm[42];
    const int cb = (int)wsm[43];

    // rb,cb <= 3 and rb+2,cb+2 <= 5 < 8: no clamps needed.
    float patch[SPAN][SPAN];
    #pragma unroll
    for (int r = 0; r < SPAN; r++)
        #pragma unroll
        for (int c = 0; c < SPAN; c++)
            patch[r][c] = g_fmt[(((rb + r) << 3) + cb + c) * CCH + ch];

    // x pass: tmp[r][ox] = sum_c patch[r][c] * xw[ox][c]
    float tmp[SPAN][OUTS];
    #pragma unroll
    for (int r = 0; r < SPAN; r++)
        #pragma unroll
        for (int ox = 0; ox < OUTS; ox++) {
            float s = patch[r][0] * wsm[21 + ox * SPAN + 0];
            s = fmaf(patch[r][1], wsm[21 + ox * SPAN + 1], s);
            s = fmaf(patch[r][2], wsm[21 + ox * SPAN + 2], s);
            tmp[r][ox] = s;
        }

    // y pass, staged into smem.
    float* ob = obuf + tid * (OUTS * OUTS);
    #pragma unroll
    for (int oy = 0; oy < OUTS; oy++)
        #pragma unroll
        for (int ox = 0; ox < OUTS; ox++) {
            float s = wsm[oy * SPAN + 0] * tmp[0][ox];
            s = fmaf(wsm[oy * SPAN + 1], tmp[1][ox], s);
            s = fmaf(wsm[oy * SPAN + 2], tmp[2][ox], s);
            ob[oy * OUTS + ox] = s;
        }
    __syncthreads();

    // ---- single TMA bulk store: 25088 B smem -> contiguous gmem ----
    if (tid == 0) {
        asm volatile("fence.proxy.async.shared::cta;" ::: "memory");
        uint32_t s32;
        asm("{ .reg .u64 t; cvta.to.shared.u64 t, %1; cvt.u32.u64 %0, t; }"
            : "=r"(s32) : "l"(obuf));
        const float* dst = out + (size_t)blockIdx.x * OBUF_FLOATS;
        asm volatile(
            "cp.async.bulk.global.shared::cta.bulk_group [%0], [%1], %2;"
            :: "l"(dst), "r"(s32), "n"(OBUF_FLOATS * 4) : "memory");
        asm volatile("cp.async.bulk.commit_group;" ::: "memory");
        asm volatile("cp.async.bulk.wait_group 0;" ::: "memory");
    }
}

extern "C" void kernel_launch(void* const* d_in, const int* in_sizes, int n_in,
                              void* d_out, int out_size) {
    const float* fm    = (const float*)d_in[0];
    const float* props = (const float*)d_in[1];
    float* out = (float*)d_out;
    int N = in_sizes[1] / 4;

    prep_kernel<<<240, 128>>>(fm, props);

    // roi launched with programmatic stream serialization; its internal
    // griddepcontrol.wait orders g_wtab/g_fmt consumption.
    cudaLaunchConfig_t cfg = {};
    cfg.gridDim  = dim3(N * 2);
    cfg.blockDim = dim3(128);
    cfg.stream   = 0;
    cudaLaunchAttribute attr[1];
    attr[0].id = cudaLaunchAttributeProgrammaticStreamSerialization;
    attr[0].val.programmaticStreamSerializationAllowed = 1;
    cfg.attrs = attr;
    cfg.numAttrs = 1;
    cudaError_t e = cudaLaunchKernelEx(&cfg, roi_kernel, out);
    if (e != cudaSuccess) {
        roi_kernel<<<N * 2, 128>>>(out);
    }
}

// round 14
// speedup vs baseline: 1.0700x; 1.0700x over previous
#include <cuda_runtime.h>
#include <cstdint>

#define CCH   256
#define FH    50
#define FW    50
#define HW    (FH*FW)
#define OUTS  7
#define SPAN  3           // bilinear footprint per ROI axis (roi extent < 1 px)
#define EX    8           // extracted corner size (max index used is 5)
#define NPIX  (EX*EX)     // 64
#define OBUF_FLOATS (256 * OUTS * OUTS)   // 12544 floats = 50176 B per block

// Extracted, channel-contiguous corner of the feature map: [64 pixels][256 ch].
__device__ float g_fmt[NPIX * CCH];

// ---------------------------------------------------------------------------
// Corner extraction (16 blocks of 1024 thr), fires PDL launch_dependents.
// ---------------------------------------------------------------------------
__global__ void extract_kernel(const float* __restrict__ fm) {
    __shared__ float tile[32][33];
    int pix = blockIdx.x * 32 + threadIdx.x;        // 0..63
    int c   = blockIdx.y * 32 + threadIdx.y;
    int fmo = (pix >> 3) * FW + (pix & 7);          // 8x8 corner -> fm offset
    tile[threadIdx.y][threadIdx.x] = fm[c * HW + fmo];
    __syncthreads();
    int c2   = blockIdx.y * 32 + threadIdx.x;
    int pix2 = blockIdx.x * 32 + threadIdx.y;
    g_fmt[pix2 * CCH + c2] = tile[threadIdx.x][threadIdx.y];
    asm volatile("griddepcontrol.launch_dependents;");
}

// ---------------------------------------------------------------------------
// ROI-align: ONE ROI per block. 1024 blocks x 256 threads (8 warps), thread =
// channel. Per-warp weight setup (validated arithmetic) runs BEFORE the PDL
// wait so it overlaps the extract kernel. Staging in 50 KB dynamic smem, one
// TMA bulk store per block (ROI output is 50176 contiguous bytes).
// ---------------------------------------------------------------------------
__global__ __launch_bounds__(256, 4) void roi_kernel(
    const float* __restrict__ props, float* __restrict__ out)
{
    extern __shared__ __align__(16) float obuf[];   // 50176 B staging
    __shared__ float wts[8][2][OUTS][SPAN];   // per-warp [axis][o][r]
    __shared__ int   sbase[8][2];             // per-warp rowbase/colbase

    const int n    = blockIdx.x;
    const int tid  = threadIdx.x;
    const int wid  = tid >> 5;
    const int lane = tid & 31;

    // ---- per-warp weight setup: lanes 0..13, one per (axis, o) ----
    // Independent of g_fmt -> overlaps extract_kernel via PDL.
    if (lane < 2 * OUTS) {
        const int axis = lane >= OUTS;       // 0 = y, 1 = x
        const int o    = (axis ? lane - OUTS : lane);
        const float sc = 1.0f / 256.0f;      // SCALE applied twice in ref (exact)
        float a1 = __fmul_rn(props[n * 4 + (axis == 0 ? 1 : 0)], sc);
        float a2 = __fmul_rn(props[n * 4 + (axis == 0 ? 3 : 2)], sc);
        float roi   = fmaxf(__fadd_rn(a2, -a1), 1.0f);
        float binsz = __fdiv_rn(roi, 7.0f);
        const float Lf = 50.0f;
        const int   Li = 49;

        // base = i0 of sample 0 (i0 monotone in s).
        int base;
        {
            float v  = __fadd_rn(a1, __fmul_rn(binsz, 0.25f));
            float vc = fminf(fmaxf(v, 0.0f), Lf - 1.0f);
            base = min((int)floorf(vc), Li);
        }
        if (o == 0) sbase[wid][axis] = base;

        float w0 = 0.0f, w1 = 0.0f, w2 = 0.0f;
        #pragma unroll
        for (int k = 0; k < 2; k++) {
            int s = 2 * o + k;
            float g = ((float)s + 0.5f) * 0.5f;
            float v = __fadd_rn(a1, __fmul_rn(binsz, g));
            bool valid = (v >= -1.0f) && (v <= Lf);
            float vc = fminf(fmaxf(v, 0.0f), Lf - 1.0f);
            int i0 = min((int)floorf(vc), Li);
            int i1 = min(i0 + 1, Li);
            float l = vc - (float)i0;
            float h = 1.0f - l;
            if (!valid) { h = 0.0f; l = 0.0f; }
            int r0 = min(i0 - base, SPAN - 1);
            int r1 = min(i1 - base, SPAN - 1);
            if (r0 == 0) w0 += h; else if (r0 == 1) w1 += h; else w2 += h;
            if (r1 == 0) w0 += l; else if (r1 == 1) w1 += l; else w2 += l;
        }
        float f = (axis == 0) ? 0.25f : 1.0f;   // fold sr*sr mean into y weights
        wts[wid][axis][o][0] = w0 * f;
        wts[wid][axis][o][1] = w1 * f;
        wts[wid][axis][o][2] = w2 * f;
    }
    __syncwarp();

    // Wait for extract_kernel's g_fmt writes (PDL dependency point).
    asm volatile("griddepcontrol.wait;");

    // ---- per-channel compute (thread = channel 0..255) ----
    const int rb = sbase[wid][0];
    const int cb = sbase[wid][1];

    // rb,cb <= 3 and rb+2,cb+2 <= 5 < 8: no clamps needed.
    float patch[SPAN][SPAN];
    #pragma unroll
    for (int r = 0; r < SPAN; r++)
        #pragma unroll
        for (int c = 0; c < SPAN; c++)
            patch[r][c] = g_fmt[(((rb + r) << 3) + cb + c) * CCH + tid];

    // x pass: tmp[r][ox] = sum_c patch[r][c] * CW[ox][c]
    float tmp[SPAN][OUTS];
    #pragma unroll
    for (int r = 0; r < SPAN; r++)
        #pragma unroll
        for (int ox = 0; ox < OUTS; ox++) {
            float s = patch[r][0] * wts[wid][1][ox][0];
            s = fmaf(patch[r][1], wts[wid][1][ox][1], s);
            s = fmaf(patch[r][2], wts[wid][1][ox][2], s);
            tmp[r][ox] = s;
        }

    // y pass, staged into smem.
    float* ob = obuf + tid * (OUTS * OUTS);
    #pragma unroll
    for (int oy = 0; oy < OUTS; oy++)
        #pragma unroll
        for (int ox = 0; ox < OUTS; ox++) {
            float s = wts[wid][0][oy][0] * tmp[0][ox];
            s = fmaf(wts[wid][0][oy][1], tmp[1][ox], s);
            s = fmaf(wts[wid][0][oy][2], tmp[2][ox], s);
            ob[oy * OUTS + ox] = s;
        }
    __syncthreads();

    // ---- one TMA bulk store: 50176 B smem -> contiguous gmem (whole ROI) ----
    if (tid == 0) {
        asm volatile("fence.proxy.async.shared::cta;" ::: "memory");
        uint32_t s32;
        asm("{ .reg .u64 t; cvta.to.shared.u64 t, %1; cvt.u32.u64 %0, t; }"
            : "=r"(s32) : "l"(obuf));
        const float* dst = out + (size_t)n * OBUF_FLOATS;
        asm volatile(
            "cp.async.bulk.global.shared::cta.bulk_group [%0], [%1], %2;"
            :: "l"(dst), "r"(s32), "n"(OBUF_FLOATS * 4) : "memory");
        asm volatile("cp.async.bulk.commit_group;" ::: "memory");
        asm volatile("cp.async.bulk.wait_group 0;" ::: "memory");
    }
}

extern "C" void kernel_launch(void* const* d_in, const int* in_sizes, int n_in,
                              void* d_out, int out_size) {
    const float* fm    = (const float*)d_in[0];
    const float* props = (const float*)d_in[1];
    float* out = (float*)d_out;
    int N = in_sizes[1] / 4;
    const int SMEM = OBUF_FLOATS * 4;   // 50176 B dynamic

    static bool attr_done = false;
    if (!attr_done) {
        cudaFuncSetAttribute(roi_kernel,
            cudaFuncAttributeMaxDynamicSharedMemorySize, SMEM);
        attr_done = true;
    }

    dim3 tb(32, 32);
    dim3 tg(2, 8);                 // 64 pixels x 256 channels
    extract_kernel<<<tg, tb>>>(fm);

    cudaLaunchConfig_t cfg = {};
    cfg.gridDim          = dim3(N);
    cfg.blockDim         = dim3(256);
    cfg.dynamicSmemBytes = SMEM;
    cfg.stream           = 0;
    cudaLaunchAttribute attr[1];
    attr[0].id = cudaLaunchAttributeProgrammaticStreamSerialization;
    attr[0].val.programmaticStreamSerializationAllowed = 1;
    cfg.attrs = attr;
    cfg.numAttrs = 1;
    cudaError_t e = cudaLaunchKernelEx(&cfg, roi_kernel, props, out);
    if (e != cudaSuccess) {
        roi_kernel<<<N, 256, SMEM>>>(props, out);
    }
}